// round 1
// baseline (speedup 1.0000x reference)
#include <cuda_runtime.h>

#define NN   50000
#define NE   800000
#define FIN  128
#define NH1  8
#define HID  32
#define F1   256   // NH1*HID
#define NOUT 40

// ---------------- scratch (device globals; no allocation allowed) ----------------
__device__ float g_z1[(size_t)NN * F1];     // feat @ W1
__device__ float g_h1[(size_t)NN * F1];     // elu(agg1 + b1)
__device__ float g_z2[(size_t)NN * NOUT];   // h1 @ W2
__device__ float g_el1[NN * NH1];
__device__ float g_er1[NN * NH1];
__device__ float g_el2[NN];
__device__ float g_er2[NN];
__device__ float g_ew1[(size_t)NE * NH1];   // unnormalized exp weights, CSR slot order
__device__ float g_ew2[NE];
__device__ float g_rden1[NN * NH1];         // 1/denom (0 if empty)
__device__ float g_rden2[NN];
__device__ int   g_deg[NN];
__device__ int   g_cursor[NN];
__device__ int   g_rowptr[NN + 1];
__device__ int   g_srcs[NE];                // src node per CSR slot

// ---------------- CSR build ----------------
__global__ void zero_kernel() {
    int i = blockIdx.x * blockDim.x + threadIdx.x;
    if (i < NN) { g_deg[i] = 0; g_cursor[i] = 0; }
}

__global__ void count_kernel(const int* __restrict__ dst) {
    int e = blockIdx.x * blockDim.x + threadIdx.x;
    if (e < NE) atomicAdd(&g_deg[dst[e]], 1);
}

__global__ void scan_kernel() {
    __shared__ int sums[1024];
    int tid = threadIdx.x;
    const int chunk = (NN + 1023) / 1024;
    int start = tid * chunk;
    int end = start + chunk; if (end > NN) end = NN;
    int local = 0;
    for (int i = start; i < end && i < NN; i++) local += g_deg[i];
    sums[tid] = local;
    __syncthreads();
    for (int off = 1; off < 1024; off <<= 1) {
        int v = 0;
        if (tid >= off) v = sums[tid - off];
        __syncthreads();
        if (tid >= off) sums[tid] += v;
        __syncthreads();
    }
    int run = (tid == 0) ? 0 : sums[tid - 1];
    for (int i = start; i < end; i++) { g_rowptr[i] = run; run += g_deg[i]; }
    if (tid == 1023) g_rowptr[NN] = run;
}

__global__ void scatter_kernel(const int* __restrict__ src, const int* __restrict__ dst) {
    int e = blockIdx.x * blockDim.x + threadIdx.x;
    if (e >= NE) return;
    int d = dst[e];
    int p = atomicAdd(&g_cursor[d], 1);
    g_srcs[g_rowptr[d] + p] = src[e];
}

// ---------------- GEMM1: z1[NN,256] = feat[NN,128] @ W1[128,256] ----------------
__global__ __launch_bounds__(256) void gemm1_kernel(const float* __restrict__ A,
                                                    const float* __restrict__ B) {
    const int M = NN, N = F1, K = FIN, BM = 128, BN = 128, BK = 8;
    __shared__ float As[BK][BM];
    __shared__ float Bs[BK][BN];
    int tid = threadIdx.x;
    int brow = blockIdx.y * BM, bcol = blockIdx.x * BN;
    int tx = tid & 15, ty = tid >> 4;
    int arow = tid >> 1, acol = (tid & 1) * 4;
    int brw = tid >> 5, bcl = (tid & 31) * 4;
    float acc[8][8];
#pragma unroll
    for (int i = 0; i < 8; i++)
#pragma unroll
        for (int j = 0; j < 8; j++) acc[i][j] = 0.f;

    for (int k0 = 0; k0 < K; k0 += BK) {
        float4 av = make_float4(0.f, 0.f, 0.f, 0.f);
        int gr = brow + arow;
        if (gr < M) av = *reinterpret_cast<const float4*>(A + (size_t)gr * K + k0 + acol);
        As[acol + 0][arow] = av.x;
        As[acol + 1][arow] = av.y;
        As[acol + 2][arow] = av.z;
        As[acol + 3][arow] = av.w;
        float4 bv = *reinterpret_cast<const float4*>(B + (size_t)(k0 + brw) * N + bcol + bcl);
        *reinterpret_cast<float4*>(&Bs[brw][bcl]) = bv;
        __syncthreads();
#pragma unroll
        for (int kk = 0; kk < BK; kk++) {
            float ar8[8], br8[8];
            *reinterpret_cast<float4*>(&ar8[0]) = *reinterpret_cast<const float4*>(&As[kk][ty * 8]);
            *reinterpret_cast<float4*>(&ar8[4]) = *reinterpret_cast<const float4*>(&As[kk][ty * 8 + 4]);
            *reinterpret_cast<float4*>(&br8[0]) = *reinterpret_cast<const float4*>(&Bs[kk][tx * 8]);
            *reinterpret_cast<float4*>(&br8[4]) = *reinterpret_cast<const float4*>(&Bs[kk][tx * 8 + 4]);
#pragma unroll
            for (int i = 0; i < 8; i++)
#pragma unroll
                for (int j = 0; j < 8; j++) acc[i][j] += ar8[i] * br8[j];
        }
        __syncthreads();
    }
#pragma unroll
    for (int i = 0; i < 8; i++) {
        int r = brow + ty * 8 + i;
        if (r < M) {
            float* cp = g_z1 + (size_t)r * N + bcol + tx * 8;
#pragma unroll
            for (int j = 0; j < 8; j++) cp[j] = acc[i][j];
        }
    }
}

// ---------------- GEMM2: z2[NN,40] = h1[NN,256] @ W2[256,40] ----------------
__global__ __launch_bounds__(256) void gemm2_kernel(const float* __restrict__ W) {
    __shared__ float Ws[F1][NOUT];  // 40 KB
    int tid = threadIdx.x;
    for (int i = tid; i < F1 * NOUT; i += 256) Ws[i / NOUT][i % NOUT] = W[i];
    __syncthreads();

    int r0 = blockIdx.x * 256 + (tid >> 2) * 4;
    int c0 = (tid & 3) * 10;
    float acc[4][10];
#pragma unroll
    for (int i = 0; i < 4; i++)
#pragma unroll
        for (int j = 0; j < 10; j++) acc[i][j] = 0.f;

    bool valid[4];
    const float* ap[4];
#pragma unroll
    for (int i = 0; i < 4; i++) {
        valid[i] = (r0 + i) < NN;
        ap[i] = g_h1 + (size_t)(valid[i] ? (r0 + i) : 0) * F1;
    }
    for (int k0 = 0; k0 < F1; k0 += 4) {
        float4 av[4];
#pragma unroll
        for (int i = 0; i < 4; i++)
            av[i] = valid[i] ? *reinterpret_cast<const float4*>(ap[i] + k0)
                             : make_float4(0.f, 0.f, 0.f, 0.f);
#pragma unroll
        for (int kk = 0; kk < 4; kk++) {
            float a[4];
#pragma unroll
            for (int i = 0; i < 4; i++) a[i] = reinterpret_cast<const float*>(&av[i])[kk];
#pragma unroll
            for (int j = 0; j < 10; j++) {
                float wv = Ws[k0 + kk][c0 + j];
#pragma unroll
                for (int i = 0; i < 4; i++) acc[i][j] += a[i] * wv;
            }
        }
    }
#pragma unroll
    for (int i = 0; i < 4; i++) {
        if (r0 + i < NN) {
            float* cp = g_z2 + (size_t)(r0 + i) * NOUT + c0;
#pragma unroll
            for (int j = 0; j < 10; j++) cp[j] = acc[i][j];
        }
    }
}

// ---------------- el/er: warp per (node, head) ----------------
template <int H, int D, bool L1>
__global__ void elr_kernel(const float* __restrict__ al, const float* __restrict__ ar) {
    int w = (blockIdx.x * blockDim.x + threadIdx.x) >> 5;
    int lane = threadIdx.x & 31;
    if (w >= NN * H) return;
    int h = w % H;
    const float* z = L1 ? g_z1 : g_z2;
    const float* zp = z + (size_t)w * D;  // z[n][h][d] contiguous, w = n*H+h
    float sl = 0.f, sr = 0.f;
    for (int d = lane; d < D; d += 32) {
        float v = zp[d];
        sl += v * al[h * D + d];
        sr += v * ar[h * D + d];
    }
#pragma unroll
    for (int o = 16; o > 0; o >>= 1) {
        sl += __shfl_xor_sync(0xffffffffu, sl, o);
        sr += __shfl_xor_sync(0xffffffffu, sr, o);
    }
    if (lane == 0) {
        (L1 ? g_el1 : g_el2)[w] = sl;
        (L1 ? g_er1 : g_er2)[w] = sr;
    }
}

// ---------------- edge softmax stats: warp per dst ----------------
template <int H, bool L1>
__global__ void stats_kernel() {
    int w = (blockIdx.x * blockDim.x + threadIdx.x) >> 5;
    int lane = threadIdx.x & 31;
    if (w >= NN) return;
    const float* el = L1 ? g_el1 : g_el2;
    const float* er = L1 ? g_er1 : g_er2;
    float* ew = L1 ? g_ew1 : g_ew2;
    float* rden = L1 ? g_rden1 : g_rden2;

    int s = g_rowptr[w], e = g_rowptr[w + 1];
    float erd[H], mx[H], sm[H];
#pragma unroll
    for (int h = 0; h < H; h++) {
        erd[h] = er[w * H + h];
        mx[h] = -1e30f;
        sm[h] = 0.f;
    }
    for (int i = s + lane; i < e; i += 32) {
        int src = g_srcs[i];
#pragma unroll
        for (int h = 0; h < H; h++) {
            float v = el[src * H + h] + erd[h];
            v = v > 0.f ? v : 0.2f * v;
            mx[h] = fmaxf(mx[h], v);
        }
    }
#pragma unroll
    for (int h = 0; h < H; h++)
#pragma unroll
        for (int o = 16; o > 0; o >>= 1) mx[h] = fmaxf(mx[h], __shfl_xor_sync(0xffffffffu, mx[h], o));
    for (int i = s + lane; i < e; i += 32) {
        int src = g_srcs[i];
#pragma unroll
        for (int h = 0; h < H; h++) {
            float v = el[src * H + h] + erd[h];
            v = v > 0.f ? v : 0.2f * v;
            float x = __expf(v - mx[h]);
            ew[(size_t)i * H + h] = x;
            sm[h] += x;
        }
    }
#pragma unroll
    for (int h = 0; h < H; h++)
#pragma unroll
        for (int o = 16; o > 0; o >>= 1) sm[h] += __shfl_xor_sync(0xffffffffu, sm[h], o);
    if (lane == 0) {
#pragma unroll
        for (int h = 0; h < H; h++) rden[w * H + h] = sm[h] > 0.f ? 1.f / sm[h] : 0.f;
    }
}

// ---------------- layer-1 aggregation: block(256) per dst, + bias + elu ----------------
__global__ __launch_bounds__(256) void agg1_kernel(const float* __restrict__ b1) {
    int dst = blockIdx.x;
    int tid = threadIdx.x;
    int h = tid >> 5;
    int s = g_rowptr[dst], e = g_rowptr[dst + 1];
    float acc = 0.f;
#pragma unroll 4
    for (int i = s; i < e; i++) {
        int src = g_srcs[i];
        float wv = g_ew1[(size_t)i * NH1 + h];
        acc += wv * g_z1[(size_t)src * F1 + tid];
    }
    float o = acc * g_rden1[dst * NH1 + h] + b1[tid];
    g_h1[(size_t)dst * F1 + tid] = o > 0.f ? o : (__expf(o) - 1.f);
}

// ---------------- layer-2 aggregation -> output ----------------
__global__ __launch_bounds__(64) void agg2_kernel(const float* __restrict__ b2,
                                                  float* __restrict__ out) {
    int dst = blockIdx.x;
    int tid = threadIdx.x;
    int s = g_rowptr[dst], e = g_rowptr[dst + 1];
    float acc = 0.f;
#pragma unroll 4
    for (int i = s; i < e; i++) {
        int src = g_srcs[i];
        float wv = g_ew2[i];
        if (tid < NOUT) acc += wv * g_z2[(size_t)src * NOUT + tid];
    }
    if (tid < NOUT) out[dst * NOUT + tid] = acc * g_rden2[dst] + b2[tid];
}

// ---------------- launch ----------------
extern "C" void kernel_launch(void* const* d_in, const int* in_sizes, int n_in,
                              void* d_out, int out_size) {
    const float* feat = (const float*)d_in[0];
    const int* src = (const int*)d_in[1];
    const int* dst = (const int*)d_in[2];
    const float* W1 = (const float*)d_in[3];
    const float* al1 = (const float*)d_in[4];
    const float* ar1 = (const float*)d_in[5];
    const float* b1 = (const float*)d_in[6];
    const float* W2 = (const float*)d_in[7];
    const float* al2 = (const float*)d_in[8];
    const float* ar2 = (const float*)d_in[9];
    const float* b2 = (const float*)d_in[10];
    float* out = (float*)d_out;

    // CSR by destination
    zero_kernel<<<(NN + 255) / 256, 256>>>();
    count_kernel<<<(NE + 255) / 256, 256>>>(dst);
    scan_kernel<<<1, 1024>>>();
    scatter_kernel<<<(NE + 255) / 256, 256>>>(src, dst);

    // layer 1
    gemm1_kernel<<<dim3(2, (NN + 127) / 128), 256>>>(feat, W1);
    elr_kernel<NH1, HID, true><<<(NN * NH1 + 7) / 8, 256>>>(al1, ar1);
    stats_kernel<NH1, true><<<(NN + 7) / 8, 256>>>();
    agg1_kernel<<<NN, 256>>>(b1);

    // layer 2
    gemm2_kernel<<<(NN + 255) / 256, 256>>>(W2);
    elr_kernel<1, NOUT, false><<<(NN + 7) / 8, 256>>>(al2, ar2);
    stats_kernel<1, false><<<(NN + 7) / 8, 256>>>();
    agg2_kernel<<<NN, 64>>>(b2, out);
}

// round 2
// speedup vs baseline: 1.1933x; 1.1933x over previous
#include <cuda_runtime.h>

#define NN   50000
#define NE   800000
#define FIN  128
#define NH1  8
#define HID  32
#define F1   256   // NH1*HID
#define NOUT 40

// ---------------- scratch (device globals; no allocation allowed) ----------------
__device__ float g_z1[(size_t)NN * F1];     // feat @ W1
__device__ float g_h1[(size_t)NN * F1];     // elu(agg1 + b1)
__device__ float g_z2[(size_t)NN * NOUT];   // h1 @ W2
__device__ float g_el1[NN * NH1];
__device__ float g_er1[NN * NH1];
__device__ float g_el2[NN];
__device__ float g_er2[NN];
__device__ float g_ew1[(size_t)NE * NH1];   // unnormalized exp weights, CSR slot order
__device__ float g_ew2[NE];
__device__ float g_rden1[NN * NH1];         // 1/denom (0 if empty)
__device__ float g_rden2[NN];
__device__ int   g_deg[NN];
__device__ int   g_cursor[NN];
__device__ int   g_rowptr[NN + 1];
__device__ int   g_srcs[NE];                // src node per CSR slot

// ---------------- CSR build ----------------
__global__ void zero_kernel() {
    int i = blockIdx.x * blockDim.x + threadIdx.x;
    if (i < NN) { g_deg[i] = 0; g_cursor[i] = 0; }
}

__global__ void count_kernel(const int* __restrict__ dst) {
    int e = blockIdx.x * blockDim.x + threadIdx.x;
    if (e < NE) atomicAdd(&g_deg[dst[e]], 1);
}

__global__ void scan_kernel() {
    __shared__ int sums[1024];
    int tid = threadIdx.x;
    const int chunk = (NN + 1023) / 1024;
    int start = tid * chunk;
    int end = start + chunk; if (end > NN) end = NN;
    int local = 0;
    for (int i = start; i < end && i < NN; i++) local += g_deg[i];
    sums[tid] = local;
    __syncthreads();
    for (int off = 1; off < 1024; off <<= 1) {
        int v = 0;
        if (tid >= off) v = sums[tid - off];
        __syncthreads();
        if (tid >= off) sums[tid] += v;
        __syncthreads();
    }
    int run = (tid == 0) ? 0 : sums[tid - 1];
    for (int i = start; i < end; i++) { g_rowptr[i] = run; run += g_deg[i]; }
    if (tid == 1023) g_rowptr[NN] = run;
}

__global__ void scatter_kernel(const int* __restrict__ src, const int* __restrict__ dst) {
    int e = blockIdx.x * blockDim.x + threadIdx.x;
    if (e >= NE) return;
    int d = dst[e];
    int p = atomicAdd(&g_cursor[d], 1);
    g_srcs[g_rowptr[d] + p] = src[e];
}

// ---------------- GEMM1: z1[NN,256] = feat[NN,128] @ W1[128,256] ----------------
// Double-buffered smem, BK=16, fused el1/er1 epilogue.
__global__ __launch_bounds__(256) void gemm1_kernel(const float* __restrict__ A,
                                                    const float* __restrict__ B,
                                                    const float* __restrict__ al,
                                                    const float* __restrict__ ar) {
    const int K = FIN, N = F1, BK = 16;
    __shared__ float As[2][BK][128];
    __shared__ float Bs[2][BK][128];
    int tid = threadIdx.x;
    int brow = blockIdx.y * 128, bcol = blockIdx.x * 128;
    int tx = tid & 15, ty = tid >> 4;

    // load mappings
    int arow = tid & 127;            // 0..127 (lane-distinct -> conflict-free smem store)
    int ak = (tid >> 7) * 8;         // 0 or 8
    int brw = tid >> 4;              // 0..15
    int bcl = (tid & 15) * 8;        // 0..120

    int gr = brow + arow;
    bool rok = gr < NN;
    const float* Ap = A + (size_t)(rok ? gr : 0) * K;

    float acc[8][8];
#pragma unroll
    for (int i = 0; i < 8; i++)
#pragma unroll
        for (int j = 0; j < 8; j++) acc[i][j] = 0.f;

    float4 pa0, pa1, pb0, pb1;
    const float4 z4 = make_float4(0.f, 0.f, 0.f, 0.f);

    // prefetch tile 0
    pa0 = rok ? *reinterpret_cast<const float4*>(Ap + ak) : z4;
    pa1 = rok ? *reinterpret_cast<const float4*>(Ap + ak + 4) : z4;
    pb0 = *reinterpret_cast<const float4*>(B + (size_t)brw * N + bcol + bcl);
    pb1 = *reinterpret_cast<const float4*>(B + (size_t)brw * N + bcol + bcl + 4);
    {
        As[0][ak + 0][arow] = pa0.x; As[0][ak + 1][arow] = pa0.y;
        As[0][ak + 2][arow] = pa0.z; As[0][ak + 3][arow] = pa0.w;
        As[0][ak + 4][arow] = pa1.x; As[0][ak + 5][arow] = pa1.y;
        As[0][ak + 6][arow] = pa1.z; As[0][ak + 7][arow] = pa1.w;
        *reinterpret_cast<float4*>(&Bs[0][brw][bcl]) = pb0;
        *reinterpret_cast<float4*>(&Bs[0][brw][bcl + 4]) = pb1;
    }
    __syncthreads();

    int buf = 0;
    for (int k0 = 0; k0 < K; k0 += BK) {
        bool more = (k0 + BK) < K;
        if (more) {
            int kn = k0 + BK;
            pa0 = rok ? *reinterpret_cast<const float4*>(Ap + kn + ak) : z4;
            pa1 = rok ? *reinterpret_cast<const float4*>(Ap + kn + ak + 4) : z4;
            pb0 = *reinterpret_cast<const float4*>(B + (size_t)(kn + brw) * N + bcol + bcl);
            pb1 = *reinterpret_cast<const float4*>(B + (size_t)(kn + brw) * N + bcol + bcl + 4);
        }
#pragma unroll
        for (int kk = 0; kk < BK; kk++) {
            float ar8[8], br8[8];
            *reinterpret_cast<float4*>(&ar8[0]) = *reinterpret_cast<const float4*>(&As[buf][kk][ty * 8]);
            *reinterpret_cast<float4*>(&ar8[4]) = *reinterpret_cast<const float4*>(&As[buf][kk][ty * 8 + 4]);
            *reinterpret_cast<float4*>(&br8[0]) = *reinterpret_cast<const float4*>(&Bs[buf][kk][tx * 8]);
            *reinterpret_cast<float4*>(&br8[4]) = *reinterpret_cast<const float4*>(&Bs[buf][kk][tx * 8 + 4]);
#pragma unroll
            for (int i = 0; i < 8; i++)
#pragma unroll
                for (int j = 0; j < 8; j++) acc[i][j] += ar8[i] * br8[j];
        }
        if (more) {
            int nb = buf ^ 1;
            As[nb][ak + 0][arow] = pa0.x; As[nb][ak + 1][arow] = pa0.y;
            As[nb][ak + 2][arow] = pa0.z; As[nb][ak + 3][arow] = pa0.w;
            As[nb][ak + 4][arow] = pa1.x; As[nb][ak + 5][arow] = pa1.y;
            As[nb][ak + 6][arow] = pa1.z; As[nb][ak + 7][arow] = pa1.w;
            *reinterpret_cast<float4*>(&Bs[nb][brw][bcl]) = pb0;
            *reinterpret_cast<float4*>(&Bs[nb][brw][bcl + 4]) = pb1;
            __syncthreads();
            buf = nb;
        }
    }

    // fused epilogue: write z1 rows + el/er partials
    int head = (bcol >> 5) + (tx >> 2);   // 0..7
    int cw = (tx & 3) * 8;                // col-within-head base
    float alv[8], arv[8];
#pragma unroll
    for (int j = 0; j < 8; j++) {
        alv[j] = al[head * HID + cw + j];
        arv[j] = ar[head * HID + cw + j];
    }
#pragma unroll
    for (int i = 0; i < 8; i++) {
        int r = brow + ty * 8 + i;
        float pl = 0.f, pr = 0.f;
#pragma unroll
        for (int j = 0; j < 8; j++) { pl += acc[i][j] * alv[j]; pr += acc[i][j] * arv[j]; }
        pl += __shfl_xor_sync(0xffffffffu, pl, 1);
        pl += __shfl_xor_sync(0xffffffffu, pl, 2);
        pr += __shfl_xor_sync(0xffffffffu, pr, 1);
        pr += __shfl_xor_sync(0xffffffffu, pr, 2);
        if (r < NN) {
            float* cp = g_z1 + (size_t)r * N + bcol + tx * 8;
            *reinterpret_cast<float4*>(cp) = *reinterpret_cast<float4*>(&acc[i][0]);
            *reinterpret_cast<float4*>(cp + 4) = *reinterpret_cast<float4*>(&acc[i][4]);
            if ((tx & 3) == 0) {
                g_el1[r * NH1 + head] = pl;
                g_er1[r * NH1 + head] = pr;
            }
        }
    }
}

// ---------------- GEMM2: z2[NN,40] = h1[NN,256] @ W2[256,40], fused el2/er2 ----------------
__global__ __launch_bounds__(256) void gemm2_kernel(const float* __restrict__ W,
                                                    const float* __restrict__ al2,
                                                    const float* __restrict__ ar2) {
    __shared__ float Ws[F1][NOUT];  // 40 KB
    int tid = threadIdx.x;
    for (int i = tid; i < F1 * NOUT; i += 256) Ws[i / NOUT][i % NOUT] = W[i];
    __syncthreads();

    int r0 = blockIdx.x * 256 + (tid >> 2) * 4;
    int c0 = (tid & 3) * 10;
    float acc[4][10];
#pragma unroll
    for (int i = 0; i < 4; i++)
#pragma unroll
        for (int j = 0; j < 10; j++) acc[i][j] = 0.f;

    bool valid[4];
    const float* ap[4];
#pragma unroll
    for (int i = 0; i < 4; i++) {
        valid[i] = (r0 + i) < NN;
        ap[i] = g_h1 + (size_t)(valid[i] ? (r0 + i) : 0) * F1;
    }
    for (int k0 = 0; k0 < F1; k0 += 4) {
        float4 av[4];
#pragma unroll
        for (int i = 0; i < 4; i++)
            av[i] = valid[i] ? *reinterpret_cast<const float4*>(ap[i] + k0)
                             : make_float4(0.f, 0.f, 0.f, 0.f);
#pragma unroll
        for (int kk = 0; kk < 4; kk++) {
            float a[4];
#pragma unroll
            for (int i = 0; i < 4; i++) a[i] = reinterpret_cast<const float*>(&av[i])[kk];
#pragma unroll
            for (int j = 0; j < 10; j++) {
                float wv = Ws[k0 + kk][c0 + j];
#pragma unroll
                for (int i = 0; i < 4; i++) acc[i][j] += a[i] * wv;
            }
        }
    }

    float alv[10], arv[10];
#pragma unroll
    for (int j = 0; j < 10; j++) { alv[j] = al2[c0 + j]; arv[j] = ar2[c0 + j]; }
#pragma unroll
    for (int i = 0; i < 4; i++) {
        float pl = 0.f, pr = 0.f;
#pragma unroll
        for (int j = 0; j < 10; j++) { pl += acc[i][j] * alv[j]; pr += acc[i][j] * arv[j]; }
        pl += __shfl_xor_sync(0xffffffffu, pl, 1);
        pl += __shfl_xor_sync(0xffffffffu, pl, 2);
        pr += __shfl_xor_sync(0xffffffffu, pr, 1);
        pr += __shfl_xor_sync(0xffffffffu, pr, 2);
        int r = r0 + i;
        if (r < NN) {
            float* cp = g_z2 + (size_t)r * NOUT + c0;
#pragma unroll
            for (int j = 0; j < 10; j++) cp[j] = acc[i][j];
            if ((tid & 3) == 0) { g_el2[r] = pl; g_er2[r] = pr; }
        }
    }
}

// ---------------- edge softmax stats: warp per dst ----------------
template <int H, bool L1>
__global__ void stats_kernel() {
    int w = (blockIdx.x * blockDim.x + threadIdx.x) >> 5;
    int lane = threadIdx.x & 31;
    if (w >= NN) return;
    const float* el = L1 ? g_el1 : g_el2;
    const float* er = L1 ? g_er1 : g_er2;
    float* ew = L1 ? g_ew1 : g_ew2;
    float* rden = L1 ? g_rden1 : g_rden2;

    int s = g_rowptr[w], e = g_rowptr[w + 1];
    float erd[H], mx[H], sm[H];
#pragma unroll
    for (int h = 0; h < H; h++) {
        erd[h] = er[w * H + h];
        mx[h] = -1e30f;
        sm[h] = 0.f;
    }
    for (int i = s + lane; i < e; i += 32) {
        int src = g_srcs[i];
#pragma unroll
        for (int h = 0; h < H; h++) {
            float v = el[src * H + h] + erd[h];
            v = v > 0.f ? v : 0.2f * v;
            mx[h] = fmaxf(mx[h], v);
        }
    }
#pragma unroll
    for (int h = 0; h < H; h++)
#pragma unroll
        for (int o = 16; o > 0; o >>= 1) mx[h] = fmaxf(mx[h], __shfl_xor_sync(0xffffffffu, mx[h], o));
    for (int i = s + lane; i < e; i += 32) {
        int src = g_srcs[i];
#pragma unroll
        for (int h = 0; h < H; h++) {
            float v = el[src * H + h] + erd[h];
            v = v > 0.f ? v : 0.2f * v;
            float x = __expf(v - mx[h]);
            ew[(size_t)i * H + h] = x;
            sm[h] += x;
        }
    }
#pragma unroll
    for (int h = 0; h < H; h++)
#pragma unroll
        for (int o = 16; o > 0; o >>= 1) sm[h] += __shfl_xor_sync(0xffffffffu, sm[h], o);
    if (lane == 0) {
#pragma unroll
        for (int h = 0; h < H; h++) rden[w * H + h] = sm[h] > 0.f ? 1.f / sm[h] : 0.f;
    }
}

// ---------------- layer-1 aggregation: block(256) per dst, + bias + elu ----------------
__global__ __launch_bounds__(256) void agg1_kernel(const float* __restrict__ b1) {
    int dst = blockIdx.x;
    int tid = threadIdx.x;
    int h = tid >> 5;
    int s = g_rowptr[dst], e = g_rowptr[dst + 1];
    float acc = 0.f;
    int i = s;
    for (; i + 4 <= e; i += 4) {
        int s0 = g_srcs[i], s1 = g_srcs[i + 1], s2 = g_srcs[i + 2], s3 = g_srcs[i + 3];
        float w0 = g_ew1[(size_t)i * NH1 + h];
        float w1 = g_ew1[(size_t)(i + 1) * NH1 + h];
        float w2 = g_ew1[(size_t)(i + 2) * NH1 + h];
        float w3 = g_ew1[(size_t)(i + 3) * NH1 + h];
        float v0 = g_z1[(size_t)s0 * F1 + tid];
        float v1 = g_z1[(size_t)s1 * F1 + tid];
        float v2 = g_z1[(size_t)s2 * F1 + tid];
        float v3 = g_z1[(size_t)s3 * F1 + tid];
        acc = fmaf(w0, v0, acc); acc = fmaf(w1, v1, acc);
        acc = fmaf(w2, v2, acc); acc = fmaf(w3, v3, acc);
    }
    for (; i < e; i++) {
        int src = g_srcs[i];
        acc = fmaf(g_ew1[(size_t)i * NH1 + h], g_z1[(size_t)src * F1 + tid], acc);
    }
    float o = acc * g_rden1[dst * NH1 + h] + b1[tid];
    g_h1[(size_t)dst * F1 + tid] = o > 0.f ? o : (__expf(o) - 1.f);
}

// ---------------- layer-2 aggregation -> output ----------------
__global__ __launch_bounds__(64) void agg2_kernel(const float* __restrict__ b2,
                                                  float* __restrict__ out) {
    int dst = blockIdx.x;
    int tid = threadIdx.x;
    int s = g_rowptr[dst], e = g_rowptr[dst + 1];
    float acc = 0.f;
    if (tid < NOUT) {
        int i = s;
        for (; i + 4 <= e; i += 4) {
            int s0 = g_srcs[i], s1 = g_srcs[i + 1], s2 = g_srcs[i + 2], s3 = g_srcs[i + 3];
            float w0 = g_ew2[i], w1 = g_ew2[i + 1], w2 = g_ew2[i + 2], w3 = g_ew2[i + 3];
            float v0 = g_z2[(size_t)s0 * NOUT + tid];
            float v1 = g_z2[(size_t)s1 * NOUT + tid];
            float v2 = g_z2[(size_t)s2 * NOUT + tid];
            float v3 = g_z2[(size_t)s3 * NOUT + tid];
            acc = fmaf(w0, v0, acc); acc = fmaf(w1, v1, acc);
            acc = fmaf(w2, v2, acc); acc = fmaf(w3, v3, acc);
        }
        for (; i < e; i++) acc = fmaf(g_ew2[i], g_z2[(size_t)g_srcs[i] * NOUT + tid], acc);
        out[dst * NOUT + tid] = acc * g_rden2[dst] + b2[tid];
    }
}

// ---------------- launch ----------------
extern "C" void kernel_launch(void* const* d_in, const int* in_sizes, int n_in,
                              void* d_out, int out_size) {
    const float* feat = (const float*)d_in[0];
    const int* src = (const int*)d_in[1];
    const int* dst = (const int*)d_in[2];
    const float* W1 = (const float*)d_in[3];
    const float* al1 = (const float*)d_in[4];
    const float* ar1 = (const float*)d_in[5];
    const float* b1 = (const float*)d_in[6];
    const float* W2 = (const float*)d_in[7];
    const float* al2 = (const float*)d_in[8];
    const float* ar2 = (const float*)d_in[9];
    const float* b2 = (const float*)d_in[10];
    float* out = (float*)d_out;

    // CSR by destination
    zero_kernel<<<(NN + 255) / 256, 256>>>();
    count_kernel<<<(NE + 255) / 256, 256>>>(dst);
    scan_kernel<<<1, 1024>>>();
    scatter_kernel<<<(NE + 255) / 256, 256>>>(src, dst);

    // layer 1
    gemm1_kernel<<<dim3(2, (NN + 127) / 128), 256>>>(feat, W1, al1, ar1);
    stats_kernel<NH1, true><<<(NN + 7) / 8, 256>>>();
    agg1_kernel<<<NN, 256>>>(b1);

    // layer 2
    gemm2_kernel<<<(NN + 255) / 256, 256>>>(W2, al2, ar2);
    stats_kernel<1, false><<<(NN + 7) / 8, 256>>>();
    agg2_kernel<<<NN, 64>>>(b2, out);
}